// round 16
// baseline (speedup 1.0000x reference)
#include <cuda_runtime.h>
#include <cuda_bf16.h>
#include <cstdint>

#define N_NODES 50000
#define N_EDGES 800000
#define DIN     369
#define D       128
#define D3      384
#define TT      13
#define STEPS   8
#define NG      256
#define NTILE32 1563             // ceil(50000/32)
#define NROWS   (TT * N_NODES)   // 650000
#define NBLK    635              // ceil(NROWS/1024)
#define HSZ     ((size_t)TT * N_NODES * D)

// ================= static scratch =================
__device__ float d_H[2 * TT * N_NODES * D];             // ping-pong hidden (666 MB)
__device__ float d_Q[TT * STEPS * D * D3];
__device__ float d_R[TT * D * D3];
__device__ __align__(16) __nv_bfloat16 d_Bs[(size_t)TT * STEPS * 512 * 256]; // [ts][n][k]
__device__ int   d_rowptr[NROWS + 1];
__device__ int   d_rcnt[NROWS];
__device__ int   d_rcur[NROWS];
__device__ int   d_col[N_EDGES];
__device__ int   d_bsum[NBLK + 1];
__device__ float d_pool[NG * D];
__device__ float d_cnt[NG];

// ================= helpers =================
__device__ __forceinline__ uint32_t smem_u32(const void* p) {
    uint32_t a;
    asm("{ .reg .u64 t; cvta.to.shared.u64 t, %1; cvt.u32.u64 %0, t; }" : "=r"(a) : "l"(p));
    return a;
}
__device__ __forceinline__ void ldsm4(uint32_t a[4], uint32_t addr) {
    asm volatile("ldmatrix.sync.aligned.m8n8.x4.shared.b16 {%0,%1,%2,%3}, [%4];"
                 : "=r"(a[0]), "=r"(a[1]), "=r"(a[2]), "=r"(a[3]) : "r"(addr));
}
__device__ __forceinline__ void mma16816(float c[4], const uint32_t a[4],
                                         uint32_t b0, uint32_t b1) {
    asm volatile("mma.sync.aligned.m16n8k16.row.col.f32.bf16.bf16.f32 "
                 "{%0,%1,%2,%3}, {%4,%5,%6,%7}, {%8,%9}, {%0,%1,%2,%3};"
                 : "+f"(c[0]), "+f"(c[1]), "+f"(c[2]), "+f"(c[3])
                 : "r"(a[0]), "r"(a[1]), "r"(a[2]), "r"(a[3]), "r"(b0), "r"(b1));
}
__device__ __forceinline__ unsigned bf2pack(float a, float b) {
    __nv_bfloat16 x = __float2bfloat16(a), y = __float2bfloat16(b);
    return (unsigned)__bfloat16_as_ushort(x) | ((unsigned)__bfloat16_as_ushort(y) << 16);
}
__device__ __forceinline__ float grustep(float rv, float zv, float iv, float gv, float h) {
    float r = 1.f / (1.f + __expf(-rv));
    float z = 1.f / (1.f + __expf(-zv));
    float n = tanhf(iv + r * gv);
    return (1.f - z) * n + z * h;
}

// ================= init / CSR =================
__global__ void k_prep() {
    for (int i = blockIdx.x * blockDim.x + threadIdx.x; i < NROWS;
         i += gridDim.x * blockDim.x) {
        d_rcnt[i] = 0;
        d_rcur[i] = 0;
        if (i < NG) d_cnt[i] = 0.f;
        if (i < NG * D) d_pool[i] = 0.f;
    }
}
__global__ void k_cnt2(const int* __restrict__ eidx, const int* __restrict__ eattr) {
    int e = blockIdx.x * blockDim.x + threadIdx.x;
    if (e >= N_EDGES) return;
    int key = eattr[e] * N_NODES + eidx[N_EDGES + e];
    atomicAdd(&d_rcnt[key], 1);
}
__global__ void k_scan1() {
    __shared__ int ws[32];
    int i = blockIdx.x * 1024 + threadIdx.x;
    int lane = threadIdx.x & 31, w = threadIdx.x >> 5;
    int v = (i < NROWS) ? d_rcnt[i] : 0;
#pragma unroll
    for (int o = 16; o; o >>= 1) v += __shfl_down_sync(0xffffffffu, v, o);
    if (lane == 0) ws[w] = v;
    __syncthreads();
    if (w == 0) {
        int x = ws[lane];
#pragma unroll
        for (int o = 16; o; o >>= 1) x += __shfl_down_sync(0xffffffffu, x, o);
        if (lane == 0) d_bsum[blockIdx.x] = x;
    }
}
__global__ void k_scan2() {
    __shared__ int ws[32];
    int i = threadIdx.x, lane = i & 31, w = i >> 5;
    int v = (i < NBLK) ? d_bsum[i] : 0;
    int inc = v;
#pragma unroll
    for (int o = 1; o < 32; o <<= 1) {
        int u = __shfl_up_sync(0xffffffffu, inc, o);
        if (lane >= o) inc += u;
    }
    if (lane == 31) ws[w] = inc;
    __syncthreads();
    if (w == 0) {
        int x = ws[lane];
#pragma unroll
        for (int o = 1; o < 32; o <<= 1) {
            int u = __shfl_up_sync(0xffffffffu, x, o);
            if (lane >= o) x += u;
        }
        ws[lane] = x;
    }
    __syncthreads();
    int excl = (w ? ws[w - 1] : 0) + inc - v;
    if (i < NBLK) d_bsum[i] = excl;
    if (i == 0) d_rowptr[NROWS] = N_EDGES;
}
__global__ void k_scan3() {
    __shared__ int ws[32];
    int i = blockIdx.x * 1024 + threadIdx.x;
    int lane = threadIdx.x & 31, w = threadIdx.x >> 5;
    int v = (i < NROWS) ? d_rcnt[i] : 0;
    int inc = v;
#pragma unroll
    for (int o = 1; o < 32; o <<= 1) {
        int u = __shfl_up_sync(0xffffffffu, inc, o);
        if (lane >= o) inc += u;
    }
    if (lane == 31) ws[w] = inc;
    __syncthreads();
    if (w == 0) {
        int x = ws[lane];
#pragma unroll
        for (int o = 1; o < 32; o <<= 1) {
            int u = __shfl_up_sync(0xffffffffu, x, o);
            if (lane >= o) x += u;
        }
        ws[lane] = x;
    }
    __syncthreads();
    int excl = d_bsum[blockIdx.x] + (w ? ws[w - 1] : 0) + inc - v;
    if (i < NROWS) d_rowptr[i] = excl;
}
__global__ void k_fill2(const int* __restrict__ eidx, const int* __restrict__ eattr) {
    int e = blockIdx.x * blockDim.x + threadIdx.x;
    if (e >= N_EDGES) return;
    int t = eattr[e];
    int key = t * N_NODES + eidx[N_EDGES + e];
    int pos = d_rowptr[key] + atomicAdd(&d_rcur[key], 1);
    d_col[pos] = t * N_NODES + eidx[e];
}

// ================= h0 / Q / R / B prep =================
__global__ void k_h0(const float* __restrict__ x, const float* __restrict__ lw,
                     const float* __restrict__ lb) {
    __shared__ float Ash[64][17];
    __shared__ float Bsh[16][128];
    const int m0 = blockIdx.x * 64;
    const int tid = threadIdx.x;
    const int tj = tid & 31, tr = tid >> 5;
    float acc[8][4];
#pragma unroll
    for (int i = 0; i < 8; i++)
#pragma unroll
        for (int j = 0; j < 4; j++) acc[i][j] = 0.f;
    for (int c0 = 0; c0 < DIN; c0 += 16) {
#pragma unroll
        for (int i = 0; i < 4; i++) {
            int id = tid + i * 256, r = id >> 4, c = id & 15;
            int gm = m0 + r, gc = c0 + c;
            Ash[r][c] = (gm < N_NODES && gc < DIN) ? x[(size_t)gm * DIN + gc] : 0.f;
        }
#pragma unroll
        for (int i = 0; i < 8; i++) {
            int id = tid + i * 256, r = id >> 7, c = id & 127;
            int gc = c0 + r;
            Bsh[r][c] = (gc < DIN) ? lw[(size_t)gc * D + c] : 0.f;
        }
        __syncthreads();
#pragma unroll
        for (int k = 0; k < 16; k++) {
            float4 b = *(const float4*)&Bsh[k][tj * 4];
#pragma unroll
            for (int i = 0; i < 8; i++) {
                float a = Ash[tr * 8 + i][k];
                acc[i][0] += a * b.x; acc[i][1] += a * b.y;
                acc[i][2] += a * b.z; acc[i][3] += a * b.w;
            }
        }
        __syncthreads();
    }
    float4 lb4 = *(const float4*)&lb[tj * 4];
#pragma unroll
    for (int i = 0; i < 8; i++) {
        int gm = m0 + tr * 8 + i;
        if (gm >= N_NODES) continue;
        float4 v = make_float4(acc[i][0] + lb4.x, acc[i][1] + lb4.y,
                               acc[i][2] + lb4.z, acc[i][3] + lb4.w);
        *(float4*)&d_H[(size_t)gm * D + tj * 4] = v;   // single copy, buf 0
    }
}

__global__ void k_q(const float* __restrict__ W, const float* __restrict__ wih) {
    int ts = blockIdx.z, t = ts >> 3;
    int m0 = blockIdx.x * 64, n0 = blockIdx.y * 64;
    const float* A = W + (size_t)ts * D * D;
    const float* B = wih + (size_t)t * D3 * D;
    __shared__ float Ash[64][17];
    __shared__ float Bsh[16][65];
    const int tid = threadIdx.x, tj = tid & 15, tr = tid >> 4;
    float acc[4][4];
#pragma unroll
    for (int i = 0; i < 4; i++)
#pragma unroll
        for (int j = 0; j < 4; j++) acc[i][j] = 0.f;
    for (int c0 = 0; c0 < D; c0 += 16) {
#pragma unroll
        for (int i = 0; i < 4; i++) {
            int id = tid + i * 256, r = id >> 4, c = id & 15;
            Ash[r][c] = A[(size_t)(m0 + r) * D + c0 + c];
        }
#pragma unroll
        for (int i = 0; i < 4; i++) {
            int id = tid + i * 256, j = id >> 4, c = id & 15;
            Bsh[c][j] = B[(size_t)(n0 + j) * D + c0 + c];
        }
        __syncthreads();
#pragma unroll
        for (int k = 0; k < 16; k++) {
            float a[4], b[4];
#pragma unroll
            for (int i = 0; i < 4; i++) a[i] = Ash[tr * 4 + i][k];
#pragma unroll
            for (int j = 0; j < 4; j++) b[j] = Bsh[k][tj * 4 + j];
#pragma unroll
            for (int i = 0; i < 4; i++)
#pragma unroll
                for (int j = 0; j < 4; j++) acc[i][j] += a[i] * b[j];
        }
        __syncthreads();
    }
    float* Qo = d_Q + (size_t)ts * D * D3;
#pragma unroll
    for (int i = 0; i < 4; i++)
#pragma unroll
        for (int j = 0; j < 4; j++)
            Qo[(size_t)(m0 + tr * 4 + i) * D3 + n0 + tj * 4 + j] = acc[i][j];
}

__global__ void k_r(const float* __restrict__ whh) {
    int i = blockIdx.x * blockDim.x + threadIdx.x;
    if (i >= TT * D * D3) return;
    int t = i / (D * D3);
    int rem = i - t * (D * D3);
    int k = rem / D3, j = rem - k * D3;
    d_R[i] = whh[(size_t)t * D3 * D + (size_t)j * D + k];
}

__global__ void k_bsplit() {
    const size_t total = (size_t)TT * STEPS * 512 * 256;
    for (size_t idx = (size_t)blockIdx.x * blockDim.x + threadIdx.x; idx < total;
         idx += (size_t)gridDim.x * blockDim.x) {
        int k = (int)(idx & 255);
        int n = (int)((idx >> 8) & 511);
        int ts = (int)(idx >> 17);
        int t = ts >> 3;
        int gate = n >> 7, j = n & 127;
        float v;
        if (k < 128) {
            v = (gate < 3) ? d_Q[((size_t)ts * 128 + k) * 384 + gate * 128 + j] : 0.f;
        } else {
            int kh = k - 128;
            v = (gate < 2) ? d_R[((size_t)t * 128 + kh) * 384 + gate * 128 + j]
              : (gate == 2) ? 0.f
              : d_R[((size_t)t * 128 + kh) * 384 + 256 + j];
        }
        d_Bs[(size_t)ts * 512 * 256 + (size_t)n * 256 + k] = __float2bfloat16(v);
    }
}

// ================= fused gather + HMMA gates kernel (M=32, 2 CTAs/SM) ========
// dyn smem: A bf16 [2][32][24]  @0       (3072 B)
//           B bf16 [2][512][24] @3072    (49152 B)
//           Sg fp32 [32][132]   @52224   (16896 B)  (reused as i_n stash)
//           Hg fp32 [32][132]   @69120   (16896 B)  -> 86016 B
#define SG_OFF  52224
#define HG_OFF  69120
#define SM_DYN  86016

__global__ void __launch_bounds__(256, 2)
k_gates_mma(int s, const float* __restrict__ b_ih, const float* __restrict__ b_hh) {
    extern __shared__ __align__(16) char smem[];
    __shared__ float sbias[4][128];

    const int t = blockIdx.y;
    const int ts = t * STEPS + s;
    const int m0 = blockIdx.x * 32;
    const int tid = threadIdx.x;
    const int lane = tid & 31, wid = tid >> 5;
    const int wn = wid;                       // 8 warps, 16 cols per gate each
    const uint32_t sb = smem_u32(smem);

    // s==0: single h0 copy in buf0 (no t-slice); else per-t slice of buf(s&1)
    const float* __restrict__ Hr = (s == 0)
        ? d_H
        : d_H + (size_t)(s & 1) * HSZ + (size_t)t * N_NODES * D;
    float* __restrict__ Hw = d_H + (size_t)(1 - (s & 1)) * HSZ + (size_t)t * N_NODES * D;
    const float* __restrict__ HrAll = d_H + (size_t)(s & 1) * HSZ;
    const int tAdj = (s == 0) ? t * N_NODES : 0;   // gather col adjustment at s=0
    const __nv_bfloat16* __restrict__ Bg = d_Bs + (size_t)ts * 512 * 256;
    float* Sg = (float*)(smem + SG_OFF);
    float* Hg = (float*)(smem + HG_OFF);

    // ---- issue rowptr load FIRST (deepest dependent chain) ----
    const int rbase = m0 + wid * 4;
    int pv = 0;
    if (lane <= 4) {
        int idx = rbase + lane;
        if (idx > N_NODES) idx = N_NODES;
        pv = d_rowptr[t * N_NODES + idx];
    }

    if (tid < 128) {
        const float* bi = b_ih + t * D3;
        const float* bh = b_hh + t * D3;
        sbias[0][tid] = bi[tid] + bh[tid];
        sbias[1][tid] = bi[128 + tid] + bh[128 + tid];
        sbias[2][tid] = bi[256 + tid];
        sbias[3][tid] = bh[256 + tid];
    }

    // ---- stage own H rows (coalesced, high MLP): 32 rows x 32 float4 ----
#pragma unroll
    for (int i = 0; i < 4; i++) {
        int id = tid + i * 256;
        int row = id >> 5, q = id & 31;
        int node = m0 + row;
        float4 v = make_float4(0.f, 0.f, 0.f, 0.f);
        if (node < N_NODES) v = ((const float4*)(Hr + (size_t)node * D))[q];
        *(float4*)(Hg + row * 132 + q * 4) = v;
    }

    // ---- MLP gather: warp covers 4 contiguous rows -> 1 contiguous edge span ----
    {
        int ptrs[5];
#pragma unroll
        for (int i = 0; i < 5; i++) ptrs[i] = __shfl_sync(0xffffffffu, pv, i);
        const int beg = ptrs[0];
        const int n = ptrs[4] - beg;

        float4 racc[4];
#pragma unroll
        for (int i = 0; i < 4; i++) racc[i] = make_float4(0.f, 0.f, 0.f, 0.f);

        for (int base = 0; base < n; base += 32) {
            int c = 0;
            if (base + lane < n) c = d_col[beg + base + lane];   // coalesced
            int m = n - base; if (m > 32) m = 32;
            for (int j0 = 0; j0 < m; j0 += 4) {
                float4 v[4];
                int rw[4];
#pragma unroll
                for (int j = 0; j < 4; j++) {
                    int jj = j0 + j;
                    bool ok = jj < m;
                    int g = __shfl_sync(0xffffffffu, c, jj & 31) - tAdj;
                    if (ok) v[j] = ((const float4*)(HrAll + (size_t)g * D))[lane];
                    else v[j] = make_float4(0.f, 0.f, 0.f, 0.f);
                    int ge = beg + base + jj;
                    int r = 0;
#pragma unroll
                    for (int i = 1; i < 4; i++) r += (ge >= ptrs[i]) ? 1 : 0;
                    rw[j] = ok ? r : 4;
                }
#pragma unroll
                for (int j = 0; j < 4; j++)
#pragma unroll
                    for (int i = 0; i < 4; i++)
                        if (rw[j] == i) {
                            racc[i].x += v[j].x; racc[i].y += v[j].y;
                            racc[i].z += v[j].z; racc[i].w += v[j].w;
                        }
            }
        }
#pragma unroll
        for (int i = 0; i < 4; i++)
            *(float4*)(Sg + (wid * 4 + i) * 132 + lane * 4) = racc[i];
    }
    __syncthreads();            // Sg + Hg ready

    // accumulators: r, z, X (X = i_n in loop1, h_n in loop2)
    float accR[2][2][4], accZ[2][2][4], accX[2][2][4];
#pragma unroll
    for (int b = 0; b < 2; b++)
#pragma unroll
        for (int c = 0; c < 2; c++)
#pragma unroll
            for (int d = 0; d < 4; d++) {
                accR[b][c][d] = 0.f; accZ[b][c][d] = 0.f; accX[b][c][d] = 0.f;
            }

    const int arow = tid >> 3, ag2 = tid & 7;    // 32 rows x 8 k-pairs
    const int arl = (lane & 7) + ((lane >> 3) & 1) * 8;
    const int ako = (lane >> 4) * 8;
    const int bnl = (lane & 7) + (lane >> 4) * 8;
    const int bko = ((lane >> 3) & 1) * 8;

    float2 avS[2];
    uint4 bvS[2][3];

    auto loadAB = [&](int k, int slot) {
        int kg = k * 16 + ag2 * 2;
        avS[slot] = (kg < 128) ? *(const float2*)(Sg + arow * 132 + kg)
                               : *(const float2*)(Hg + arow * 132 + (kg - 128));
#pragma unroll
        for (int i = 0; i < 3; i++) {
            int id = tid + i * 256;
            int row = id >> 1, half = id & 1;
            int n = row + ((k >= 8 && row >= 256) ? 128 : 0);
            bvS[slot][i] = *(const uint4*)(Bg + (size_t)n * 256 + k * 16 + half * 8);
        }
    };
    auto storeAB = [&](int buf, int k, int slot) {
        *(unsigned*)(smem + (uint32_t)(((buf * 32 + arow) * 24 + ag2 * 2) * 2)) =
            bf2pack(avS[slot].x, avS[slot].y);
#pragma unroll
        for (int i = 0; i < 3; i++) {
            int id = tid + i * 256;
            int row = id >> 1, half = id & 1;
            int n = row + ((k >= 8 && row >= 256) ? 128 : 0);
            *(uint4*)(smem + (uint32_t)((1536 + (buf * 512 + n) * 24 + half * 8) * 2)) =
                bvS[slot][i];
        }
    };
    auto computeK = [&](int cur, int nbX) {
        uint32_t ah[2][4];
#pragma unroll
        for (int mt = 0; mt < 2; mt++)
            ldsm4(ah[mt], sb + (uint32_t)(((cur * 32 + mt * 16 + arl) * 24 + ako) * 2));
        {   // r gate: rows 0..
            uint32_t bh[4];
            ldsm4(bh, sb + (uint32_t)((1536 + (cur * 512 + wn * 16 + bnl) * 24 + bko) * 2));
#pragma unroll
            for (int mt = 0; mt < 2; mt++)
#pragma unroll
                for (int sub = 0; sub < 2; sub++)
                    mma16816(accR[mt][sub], ah[mt], bh[sub * 2], bh[sub * 2 + 1]);
        }
        {   // z gate: rows 128..
            uint32_t bh[4];
            ldsm4(bh, sb + (uint32_t)((1536 + (cur * 512 + 128 + wn * 16 + bnl) * 24 + bko) * 2));
#pragma unroll
            for (int mt = 0; mt < 2; mt++)
#pragma unroll
                for (int sub = 0; sub < 2; sub++)
                    mma16816(accZ[mt][sub], ah[mt], bh[sub * 2], bh[sub * 2 + 1]);
        }
        {   // X gate: rows nbX..
            uint32_t bh[4];
            ldsm4(bh, sb + (uint32_t)((1536 + (cur * 512 + nbX + bnl) * 24 + bko) * 2));
#pragma unroll
            for (int mt = 0; mt < 2; mt++)
#pragma unroll
                for (int sub = 0; sub < 2; sub++)
                    mma16816(accX[mt][sub], ah[mt], bh[sub * 2], bh[sub * 2 + 1]);
        }
    };

    // ---- 2-deep prefetch pipeline ----
    loadAB(0, 0);
    storeAB(0, 0, 0);
    loadAB(1, 0);
    loadAB(2, 1);
    __syncthreads();             // stage 0 visible

    const int nbI = 256 + wn * 16;   // i_n rows (loop1)
    const int nbH = 384 + wn * 16;   // h_n rows (loop2)

    // ---- loop 1: ks 0..7 (r, z, i_n) ----
#pragma unroll
    for (int ks = 0; ks < 8; ks++) {
        int cur = ks & 1;
        storeAB(cur ^ 1, ks + 1, ks & 1);   // data loaded 2 iters ago
        loadAB(ks + 3, ks & 1);             // issue for ks+3
        computeK(cur, nbI);
        __syncthreads();
    }

    // ---- stash i_n into Sg (free after ks 7), reuse regs as h_n ----
    {
        float* stash = Sg + tid * 16;
#pragma unroll
        for (int mt = 0; mt < 2; mt++)
#pragma unroll
            for (int sub = 0; sub < 2; sub++)
#pragma unroll
                for (int c = 0; c < 4; c++) {
                    stash[mt * 8 + sub * 4 + c] = accX[mt][sub][c];
                    accX[mt][sub][c] = 0.f;
                }
    }

    // ---- loop 2: ks 8..15 (r, z, h_n) ----
#pragma unroll
    for (int ks = 8; ks < 16; ks++) {
        int cur = ks & 1;
        if (ks < 15) storeAB(cur ^ 1, ks + 1, ks & 1);
        if (ks < 13) loadAB(ks + 3, ks & 1);
        computeK(cur, nbH);
        __syncthreads();
    }

    // ---- GRU epilogue: holds from Hg, i_n from stash, write in-place to Hg ----
    const int g = lane >> 2, tig = lane & 3;
    const float* stash = Sg + tid * 16;
#pragma unroll
    for (int mt = 0; mt < 2; mt++) {
#pragma unroll
        for (int half = 0; half < 2; half++) {
            int rl = mt * 16 + g + half * 8;
            float* hrow = Hg + rl * 132;
#pragma unroll
            for (int sub = 0; sub < 2; sub++) {
                int j0 = wn * 16 + sub * 8 + tig * 2;
                int c0 = half * 2;
                float h0 = hrow[j0], h1 = hrow[j0 + 1];
                float i0 = stash[mt * 8 + sub * 4 + c0];
                float i1 = stash[mt * 8 + sub * 4 + c0 + 1];
                float o0 = grustep(accR[mt][sub][c0] + sbias[0][j0],
                                   accZ[mt][sub][c0] + sbias[1][j0],
                                   i0 + sbias[2][j0],
                                   accX[mt][sub][c0] + sbias[3][j0], h0);
                float o1 = grustep(accR[mt][sub][c0 + 1] + sbias[0][j0 + 1],
                                   accZ[mt][sub][c0 + 1] + sbias[1][j0 + 1],
                                   i1 + sbias[2][j0 + 1],
                                   accX[mt][sub][c0 + 1] + sbias[3][j0 + 1], h1);
                hrow[j0] = o0;
                hrow[j0 + 1] = o1;
            }
        }
    }
    __syncthreads();

    // ---- coalesced write-out from Hg: 32 rows x 32 float4 ----
#pragma unroll
    for (int i = 0; i < 4; i++) {
        int id = tid + i * 256;
        int row = id >> 5, q = id & 31;
        int node = m0 + row;
        if (node < N_NODES)
            ((float4*)(Hw + (size_t)node * D))[q] = *(float4*)(Hg + row * 132 + q * 4);
    }
}

// ================= pooling / output (final H in buf 0) =================
__global__ void k_pool(const int* __restrict__ batch) {
    int w = (blockIdx.x * blockDim.x + threadIdx.x) >> 5;
    int lane = threadIdx.x & 31;
    if (w >= N_NODES) return;
    int g = batch[w];
    float4 acc = make_float4(0.f, 0.f, 0.f, 0.f);
    for (int t = 0; t < TT; t++) {
        float4 v = ((const float4*)(d_H + ((size_t)t * N_NODES + w) * D))[lane];
        acc.x += v.x; acc.y += v.y; acc.z += v.z; acc.w += v.w;
    }
    float* p = d_pool + (size_t)g * D + lane * 4;
    atomicAdd(p + 0, acc.x); atomicAdd(p + 1, acc.y);
    atomicAdd(p + 2, acc.z); atomicAdd(p + 3, acc.w);
    if (lane == 0) atomicAdd(&d_cnt[g], 1.f);
}

__global__ void k_out(const float* __restrict__ cw, const float* __restrict__ cb,
                      float* __restrict__ out) {
    int g = blockIdx.x, c = threadIdx.y, lane = threadIdx.x;
    float inv = 1.f / fmaxf(d_cnt[g], 1.f);
    float acc = 0.f;
    for (int j = lane; j < D; j += 32)
        acc += d_pool[(size_t)g * D + j] * inv * cw[j * 2 + c];
#pragma unroll
    for (int o = 16; o; o >>= 1) acc += __shfl_down_sync(0xffffffffu, acc, o);
    if (lane == 0) out[g * 2 + c] = acc + cb[c];
}

// ================= launch =================
extern "C" void kernel_launch(void* const* d_in, const int* in_sizes, int n_in,
                              void* d_out, int out_size) {
    const float* x      = (const float*)d_in[0];
    const int*   eidx   = (const int*)d_in[1];
    const int*   eattr  = (const int*)d_in[2];
    const int*   batch  = (const int*)d_in[3];
    const float* lin_w  = (const float*)d_in[4];
    const float* lin_b  = (const float*)d_in[5];
    const float* ggnn_w = (const float*)d_in[6];
    const float* w_ih   = (const float*)d_in[7];
    const float* w_hh   = (const float*)d_in[8];
    const float* b_ih   = (const float*)d_in[9];
    const float* b_hh   = (const float*)d_in[10];
    const float* cls_w  = (const float*)d_in[11];
    const float* cls_b  = (const float*)d_in[12];
    float* out = (float*)d_out;
    (void)in_sizes; (void)n_in; (void)out_size;

    cudaFuncSetAttribute(k_gates_mma, cudaFuncAttributeMaxDynamicSharedMemorySize, SM_DYN);

    k_prep<<<640, 256>>>();
    k_cnt2<<<(N_EDGES + 255) / 256, 256>>>(eidx, eattr);
    k_scan1<<<NBLK, 1024>>>();
    k_scan2<<<1, 1024>>>();
    k_scan3<<<NBLK, 1024>>>();
    k_fill2<<<(N_EDGES + 255) / 256, 256>>>(eidx, eattr);
    k_h0<<<(N_NODES + 63) / 64, 256>>>(x, lin_w, lin_b);
    {
        dim3 g(2, 6, TT * STEPS);
        k_q<<<g, 256>>>(ggnn_w, w_ih);
    }
    k_r<<<(TT * D * D3 + 255) / 256, 256>>>(w_hh);
    k_bsplit<<<2048, 256>>>();

    for (int s = 0; s < STEPS; s++) {
        dim3 gg(NTILE32, TT);
        k_gates_mma<<<gg, 256, SM_DYN>>>(s, b_ih, b_hh);
    }
    k_pool<<<(N_NODES * 32 + 255) / 256, 256>>>(batch);
    k_out<<<NG, dim3(32, 2)>>>(cls_w, cls_b, out);
}

// round 17
// speedup vs baseline: 1.0564x; 1.0564x over previous
#include <cuda_runtime.h>
#include <cuda_bf16.h>
#include <cstdint>

#define N_NODES 50000
#define N_EDGES 800000
#define DIN     369
#define D       128
#define D3      384
#define TT      13
#define STEPS   8
#define NG      256
#define NTILE32 1563             // ceil(50000/32)
#define NROWS   (TT * N_NODES)   // 650000
#define NBLK    635              // ceil(NROWS/1024)
#define HSZ     ((size_t)TT * N_NODES * D)

// ================= static scratch =================
__device__ float d_H[2 * TT * N_NODES * D];             // ping-pong hidden (666 MB)
__device__ float d_Q[TT * STEPS * D * D3];
__device__ float d_R[TT * D * D3];
__device__ __align__(16) __nv_bfloat16 d_Bs[(size_t)TT * STEPS * 512 * 256]; // [ts][n][k]
__device__ int   d_rowptr[NROWS + 1];
__device__ int   d_rcnt[NROWS];
__device__ int   d_rcur[NROWS];
__device__ int   d_col[N_EDGES];
__device__ int   d_bsum[NBLK + 1];
__device__ float d_pool[NG * D];
__device__ float d_cnt[NG];

// ================= helpers =================
__device__ __forceinline__ uint32_t smem_u32(const void* p) {
    uint32_t a;
    asm("{ .reg .u64 t; cvta.to.shared.u64 t, %1; cvt.u32.u64 %0, t; }" : "=r"(a) : "l"(p));
    return a;
}
__device__ __forceinline__ void ldsm4(uint32_t a[4], uint32_t addr) {
    asm volatile("ldmatrix.sync.aligned.m8n8.x4.shared.b16 {%0,%1,%2,%3}, [%4];"
                 : "=r"(a[0]), "=r"(a[1]), "=r"(a[2]), "=r"(a[3]) : "r"(addr));
}
__device__ __forceinline__ void mma16816(float c[4], const uint32_t a[4],
                                         uint32_t b0, uint32_t b1) {
    asm volatile("mma.sync.aligned.m16n8k16.row.col.f32.bf16.bf16.f32 "
                 "{%0,%1,%2,%3}, {%4,%5,%6,%7}, {%8,%9}, {%0,%1,%2,%3};"
                 : "+f"(c[0]), "+f"(c[1]), "+f"(c[2]), "+f"(c[3])
                 : "r"(a[0]), "r"(a[1]), "r"(a[2]), "r"(a[3]), "r"(b0), "r"(b1));
}
__device__ __forceinline__ unsigned bf2pack(float a, float b) {
    __nv_bfloat16 x = __float2bfloat16(a), y = __float2bfloat16(b);
    return (unsigned)__bfloat16_as_ushort(x) | ((unsigned)__bfloat16_as_ushort(y) << 16);
}
__device__ __forceinline__ float fsig(float x) {
    return __fdividef(1.f, 1.f + __expf(-x));
}
__device__ __forceinline__ float ftanh(float x) {
    return 1.f - __fdividef(2.f, __expf(2.f * x) + 1.f);
}
__device__ __forceinline__ float grustep(float rv, float zv, float iv, float gv, float h) {
    float r = fsig(rv);
    float z = fsig(zv);
    float n = ftanh(iv + r * gv);
    return (1.f - z) * n + z * h;
}

// ================= init / CSR =================
__global__ void k_prep() {
    for (int i = blockIdx.x * blockDim.x + threadIdx.x; i < NROWS;
         i += gridDim.x * blockDim.x) {
        d_rcnt[i] = 0;
        d_rcur[i] = 0;
        if (i < NG) d_cnt[i] = 0.f;
        if (i < NG * D) d_pool[i] = 0.f;
    }
}
__global__ void k_cnt2(const int* __restrict__ eidx, const int* __restrict__ eattr) {
    int e = blockIdx.x * blockDim.x + threadIdx.x;
    if (e >= N_EDGES) return;
    int key = eattr[e] * N_NODES + eidx[N_EDGES + e];
    atomicAdd(&d_rcnt[key], 1);
}
__global__ void k_scan1() {
    __shared__ int ws[32];
    int i = blockIdx.x * 1024 + threadIdx.x;
    int lane = threadIdx.x & 31, w = threadIdx.x >> 5;
    int v = (i < NROWS) ? d_rcnt[i] : 0;
#pragma unroll
    for (int o = 16; o; o >>= 1) v += __shfl_down_sync(0xffffffffu, v, o);
    if (lane == 0) ws[w] = v;
    __syncthreads();
    if (w == 0) {
        int x = ws[lane];
#pragma unroll
        for (int o = 16; o; o >>= 1) x += __shfl_down_sync(0xffffffffu, x, o);
        if (lane == 0) d_bsum[blockIdx.x] = x;
    }
}
__global__ void k_scan2() {
    __shared__ int ws[32];
    int i = threadIdx.x, lane = i & 31, w = i >> 5;
    int v = (i < NBLK) ? d_bsum[i] : 0;
    int inc = v;
#pragma unroll
    for (int o = 1; o < 32; o <<= 1) {
        int u = __shfl_up_sync(0xffffffffu, inc, o);
        if (lane >= o) inc += u;
    }
    if (lane == 31) ws[w] = inc;
    __syncthreads();
    if (w == 0) {
        int x = ws[lane];
#pragma unroll
        for (int o = 1; o < 32; o <<= 1) {
            int u = __shfl_up_sync(0xffffffffu, x, o);
            if (lane >= o) x += u;
        }
        ws[lane] = x;
    }
    __syncthreads();
    int excl = (w ? ws[w - 1] : 0) + inc - v;
    if (i < NBLK) d_bsum[i] = excl;
    if (i == 0) d_rowptr[NROWS] = N_EDGES;
}
__global__ void k_scan3() {
    __shared__ int ws[32];
    int i = blockIdx.x * 1024 + threadIdx.x;
    int lane = threadIdx.x & 31, w = threadIdx.x >> 5;
    int v = (i < NROWS) ? d_rcnt[i] : 0;
    int inc = v;
#pragma unroll
    for (int o = 1; o < 32; o <<= 1) {
        int u = __shfl_up_sync(0xffffffffu, inc, o);
        if (lane >= o) inc += u;
    }
    if (lane == 31) ws[w] = inc;
    __syncthreads();
    if (w == 0) {
        int x = ws[lane];
#pragma unroll
        for (int o = 1; o < 32; o <<= 1) {
            int u = __shfl_up_sync(0xffffffffu, x, o);
            if (lane >= o) x += u;
        }
        ws[lane] = x;
    }
    __syncthreads();
    int excl = d_bsum[blockIdx.x] + (w ? ws[w - 1] : 0) + inc - v;
    if (i < NROWS) d_rowptr[i] = excl;
}
__global__ void k_fill2(const int* __restrict__ eidx, const int* __restrict__ eattr) {
    int e = blockIdx.x * blockDim.x + threadIdx.x;
    if (e >= N_EDGES) return;
    int t = eattr[e];
    int key = t * N_NODES + eidx[N_EDGES + e];
    int pos = d_rowptr[key] + atomicAdd(&d_rcur[key], 1);
    d_col[pos] = t * N_NODES + eidx[e];
}

// ================= h0 / Q / R / B prep =================
// Writes ONE copy of h0 into d_H buf0 [0 .. N_NODES*D); step 0 reads it for all t.
__global__ void k_h0(const float* __restrict__ x, const float* __restrict__ lw,
                     const float* __restrict__ lb) {
    __shared__ float Ash[64][17];
    __shared__ float Bsh[16][128];
    const int m0 = blockIdx.x * 64;
    const int tid = threadIdx.x;
    const int tj = tid & 31, tr = tid >> 5;
    float acc[8][4];
#pragma unroll
    for (int i = 0; i < 8; i++)
#pragma unroll
        for (int j = 0; j < 4; j++) acc[i][j] = 0.f;
    for (int c0 = 0; c0 < DIN; c0 += 16) {
#pragma unroll
        for (int i = 0; i < 4; i++) {
            int id = tid + i * 256, r = id >> 4, c = id & 15;
            int gm = m0 + r, gc = c0 + c;
            Ash[r][c] = (gm < N_NODES && gc < DIN) ? x[(size_t)gm * DIN + gc] : 0.f;
        }
#pragma unroll
        for (int i = 0; i < 8; i++) {
            int id = tid + i * 256, r = id >> 7, c = id & 127;
            int gc = c0 + r;
            Bsh[r][c] = (gc < DIN) ? lw[(size_t)gc * D + c] : 0.f;
        }
        __syncthreads();
#pragma unroll
        for (int k = 0; k < 16; k++) {
            float4 b = *(const float4*)&Bsh[k][tj * 4];
#pragma unroll
            for (int i = 0; i < 8; i++) {
                float a = Ash[tr * 8 + i][k];
                acc[i][0] += a * b.x; acc[i][1] += a * b.y;
                acc[i][2] += a * b.z; acc[i][3] += a * b.w;
            }
        }
        __syncthreads();
    }
    float4 lb4 = *(const float4*)&lb[tj * 4];
#pragma unroll
    for (int i = 0; i < 8; i++) {
        int gm = m0 + tr * 8 + i;
        if (gm >= N_NODES) continue;
        float4 v = make_float4(acc[i][0] + lb4.x, acc[i][1] + lb4.y,
                               acc[i][2] + lb4.z, acc[i][3] + lb4.w);
        *(float4*)&d_H[(size_t)gm * D + tj * 4] = v;   // single copy, buf 0
    }
}

__global__ void k_q(const float* __restrict__ W, const float* __restrict__ wih) {
    int ts = blockIdx.z, t = ts >> 3;
    int m0 = blockIdx.x * 64, n0 = blockIdx.y * 64;
    const float* A = W + (size_t)ts * D * D;
    const float* B = wih + (size_t)t * D3 * D;
    __shared__ float Ash[64][17];
    __shared__ float Bsh[16][65];
    const int tid = threadIdx.x, tj = tid & 15, tr = tid >> 4;
    float acc[4][4];
#pragma unroll
    for (int i = 0; i < 4; i++)
#pragma unroll
        for (int j = 0; j < 4; j++) acc[i][j] = 0.f;
    for (int c0 = 0; c0 < D; c0 += 16) {
#pragma unroll
        for (int i = 0; i < 4; i++) {
            int id = tid + i * 256, r = id >> 4, c = id & 15;
            Ash[r][c] = A[(size_t)(m0 + r) * D + c0 + c];
        }
#pragma unroll
        for (int i = 0; i < 4; i++) {
            int id = tid + i * 256, j = id >> 4, c = id & 15;
            Bsh[c][j] = B[(size_t)(n0 + j) * D + c0 + c];
        }
        __syncthreads();
#pragma unroll
        for (int k = 0; k < 16; k++) {
            float a[4], b[4];
#pragma unroll
            for (int i = 0; i < 4; i++) a[i] = Ash[tr * 4 + i][k];
#pragma unroll
            for (int j = 0; j < 4; j++) b[j] = Bsh[k][tj * 4 + j];
#pragma unroll
            for (int i = 0; i < 4; i++)
#pragma unroll
                for (int j = 0; j < 4; j++) acc[i][j] += a[i] * b[j];
        }
        __syncthreads();
    }
    float* Qo = d_Q + (size_t)ts * D * D3;
#pragma unroll
    for (int i = 0; i < 4; i++)
#pragma unroll
        for (int j = 0; j < 4; j++)
            Qo[(size_t)(m0 + tr * 4 + i) * D3 + n0 + tj * 4 + j] = acc[i][j];
}

__global__ void k_r(const float* __restrict__ whh) {
    int i = blockIdx.x * blockDim.x + threadIdx.x;
    if (i >= TT * D * D3) return;
    int t = i / (D * D3);
    int rem = i - t * (D * D3);
    int k = rem / D3, j = rem - k * D3;
    d_R[i] = whh[(size_t)t * D3 * D + (size_t)j * D + k];
}

__global__ void k_bsplit() {
    const size_t total = (size_t)TT * STEPS * 512 * 256;
    for (size_t idx = (size_t)blockIdx.x * blockDim.x + threadIdx.x; idx < total;
         idx += (size_t)gridDim.x * blockDim.x) {
        int k = (int)(idx & 255);
        int n = (int)((idx >> 8) & 511);
        int ts = (int)(idx >> 17);
        int t = ts >> 3;
        int gate = n >> 7, j = n & 127;
        float v;
        if (k < 128) {
            v = (gate < 3) ? d_Q[((size_t)ts * 128 + k) * 384 + gate * 128 + j] : 0.f;
        } else {
            int kh = k - 128;
            v = (gate < 2) ? d_R[((size_t)t * 128 + kh) * 384 + gate * 128 + j]
              : (gate == 2) ? 0.f
              : d_R[((size_t)t * 128 + kh) * 384 + 256 + j];
        }
        d_Bs[(size_t)ts * 512 * 256 + (size_t)n * 256 + k] = __float2bfloat16(v);
    }
}

// ================= fused gather + HMMA gates kernel (M=32, 2 CTAs/SM) ========
// dyn smem: A bf16 [2][32][24]  @0       (3072 B)
//           B bf16 [2][512][24] @3072    (49152 B)
//           Sg fp32 [32][132]   @52224   (16896 B)
//           Hg fp32 [32][132]   @69120   (16896 B)  -> 86016 B
#define SG_OFF  52224
#define HG_OFF  69120
#define SM_DYN  86016

__global__ void __launch_bounds__(256, 2)
k_gates_mma(int s, const float* __restrict__ b_ih, const float* __restrict__ b_hh) {
    extern __shared__ __align__(16) char smem[];
    __shared__ float sbias[4][128];

    const int t = blockIdx.y;
    const int ts = t * STEPS + s;
    const int m0 = blockIdx.x * 32;
    const int tid = threadIdx.x;
    const int lane = tid & 31, wid = tid >> 5;
    const int wn = wid;                       // 8 warps, 16 cols per gate each
    const uint32_t sb = smem_u32(smem);

    // s==0: single h0 copy in buf0 (no t-slice); else per-t slice of buf(s&1)
    const float* __restrict__ Hr = (s == 0)
        ? d_H
        : d_H + (size_t)(s & 1) * HSZ + (size_t)t * N_NODES * D;
    float* __restrict__ Hw = d_H + (size_t)(1 - (s & 1)) * HSZ + (size_t)t * N_NODES * D;
    const float* __restrict__ HrAll = d_H + (size_t)(s & 1) * HSZ;
    const int tAdj = (s == 0) ? t * N_NODES : 0;   // gather col adjustment at s=0
    const __nv_bfloat16* __restrict__ Bg = d_Bs + (size_t)ts * 512 * 256;
    float* Sg = (float*)(smem + SG_OFF);
    float* Hg = (float*)(smem + HG_OFF);

    // ---- issue rowptr load FIRST (deepest dependent chain) ----
    const int rbase = m0 + wid * 4;
    int pv = 0;
    if (lane <= 4) {
        int idx = rbase + lane;
        if (idx > N_NODES) idx = N_NODES;
        pv = d_rowptr[t * N_NODES + idx];
    }

    if (tid < 128) {
        const float* bi = b_ih + t * D3;
        const float* bh = b_hh + t * D3;
        sbias[0][tid] = bi[tid] + bh[tid];
        sbias[1][tid] = bi[128 + tid] + bh[128 + tid];
        sbias[2][tid] = bi[256 + tid];
        sbias[3][tid] = bh[256 + tid];
    }

    // ---- stage own H rows (coalesced, high MLP): 32 rows x 32 float4 ----
#pragma unroll
    for (int i = 0; i < 4; i++) {
        int id = tid + i * 256;
        int row = id >> 5, q = id & 31;
        int node = m0 + row;
        float4 v = make_float4(0.f, 0.f, 0.f, 0.f);
        if (node < N_NODES) v = ((const float4*)(Hr + (size_t)node * D))[q];
        *(float4*)(Hg + row * 132 + q * 4) = v;
    }

    // ---- MLP gather: warp covers 4 contiguous rows -> 1 contiguous edge span ----
    {
        int ptrs[5];
#pragma unroll
        for (int i = 0; i < 5; i++) ptrs[i] = __shfl_sync(0xffffffffu, pv, i);
        const int beg = ptrs[0];
        const int n = ptrs[4] - beg;

        float4 racc[4];
#pragma unroll
        for (int i = 0; i < 4; i++) racc[i] = make_float4(0.f, 0.f, 0.f, 0.f);

        for (int base = 0; base < n; base += 32) {
            int c = 0;
            if (base + lane < n) c = d_col[beg + base + lane];   // coalesced
            int m = n - base; if (m > 32) m = 32;
            for (int j0 = 0; j0 < m; j0 += 4) {
                float4 v[4];
                int rw[4];
#pragma unroll
                for (int j = 0; j < 4; j++) {
                    int jj = j0 + j;
                    bool ok = jj < m;
                    int g = __shfl_sync(0xffffffffu, c, jj & 31) - tAdj;
                    if (ok) v[j] = ((const float4*)(HrAll + (size_t)g * D))[lane];
                    else v[j] = make_float4(0.f, 0.f, 0.f, 0.f);
                    int ge = beg + base + jj;
                    int r = 0;
#pragma unroll
                    for (int i = 1; i < 4; i++) r += (ge >= ptrs[i]) ? 1 : 0;
                    rw[j] = ok ? r : 4;
                }
#pragma unroll
                for (int j = 0; j < 4; j++)
#pragma unroll
                    for (int i = 0; i < 4; i++)
                        if (rw[j] == i) {
                            racc[i].x += v[j].x; racc[i].y += v[j].y;
                            racc[i].z += v[j].z; racc[i].w += v[j].w;
                        }
            }
        }
#pragma unroll
        for (int i = 0; i < 4; i++)
            *(float4*)(Sg + (wid * 4 + i) * 132 + lane * 4) = racc[i];
    }
    __syncthreads();            // Sg + Hg ready

    float acc[4][2][2][4];
#pragma unroll
    for (int a = 0; a < 4; a++)
#pragma unroll
        for (int b = 0; b < 2; b++)
#pragma unroll
            for (int c = 0; c < 2; c++)
#pragma unroll
                for (int d = 0; d < 4; d++) acc[a][b][c][d] = 0.f;

    const int arow = tid >> 3, ag2 = tid & 7;    // 32 rows x 8 k-pairs

    float2 av;
    uint4 bv[3];
    int bn[3];

    auto loadG = [&](int ks) {
        int kg = ks * 16 + ag2 * 2;
        if (kg < 128) {
            av = *(const float2*)(Sg + arow * 132 + kg);
        } else {
            av = *(const float2*)(Hg + arow * 132 + (kg - 128));
        }
#pragma unroll
        for (int i = 0; i < 3; i++) {
            int id = tid + i * 256;
            int row = id >> 1, half = id & 1;
            int n = row + ((ks >= 8 && row >= 256) ? 128 : 0);
            bn[i] = n;
            bv[i] = *(const uint4*)(Bg + (size_t)n * 256 + ks * 16 + half * 8);
        }
    };
    auto storeS = [&](int buf) {
        unsigned hi0 = bf2pack(av.x, av.y);
        *(unsigned*)(smem + (uint32_t)(((buf * 32 + arow) * 24 + ag2 * 2) * 2)) = hi0;
#pragma unroll
        for (int i = 0; i < 3; i++) {
            int id = tid + i * 256;
            int half = id & 1;
            uint32_t off = (uint32_t)((1536 + (buf * 512 + bn[i]) * 24 + half * 8) * 2);
            *(uint4*)(smem + off) = bv[i];
        }
    };
    auto compute = [&](int cur, int ks) {
        uint32_t ah[2][4];
        const int arl = (lane & 7) + ((lane >> 3) & 1) * 8;
        const int ako = (lane >> 4) * 8;
#pragma unroll
        for (int mt = 0; mt < 2; mt++) {
            int rb = mt * 16;
            ldsm4(ah[mt], sb + (uint32_t)(((cur * 32 + rb + arl) * 24 + ako) * 2));
        }
        const int bnl = (lane & 7) + (lane >> 4) * 8;
        const int bko = ((lane >> 3) & 1) * 8;
#pragma unroll
        for (int gi = 0; gi < 4; gi++) {
            if (gi == 2 && ks >= 8) continue;
            if (gi == 3 && ks < 8) continue;
            int nb = gi * 128 + wn * 16;
            uint32_t bh[4];
            ldsm4(bh, sb + (uint32_t)((1536 + (cur * 512 + nb + bnl) * 24 + bko) * 2));
#pragma unroll
            for (int mt = 0; mt < 2; mt++)
#pragma unroll
                for (int sub = 0; sub < 2; sub++)
                    mma16816(acc[gi][mt][sub], ah[mt],
                             bh[sub * 2], bh[sub * 2 + 1]);
        }
    };

    loadG(0);
    storeS(0);
    __syncthreads();
    for (int ks = 0; ks < 16; ks++) {
        int cur = ks & 1;
        if (ks < 15) loadG(ks + 1);
        compute(cur, ks);
        if (ks < 15) storeS(cur ^ 1);
        __syncthreads();
    }

    // ---- GRU epilogue: holds from Hg, stage outputs into Sg ----
    const int g = lane >> 2, tig = lane & 3;
#pragma unroll
    for (int mt = 0; mt < 2; mt++) {
#pragma unroll
        for (int half = 0; half < 2; half++) {
            int rl = mt * 16 + g + half * 8;
            const float* hrow = Hg + rl * 132;
            float* orow = Sg + rl * 132;
#pragma unroll
            for (int sub = 0; sub < 2; sub++) {
                int j0 = wn * 16 + sub * 8 + tig * 2;
                int c0 = half * 2;
                float h0 = hrow[j0], h1 = hrow[j0 + 1];
                float o0 = grustep(acc[0][mt][sub][c0] + sbias[0][j0],
                                   acc[1][mt][sub][c0] + sbias[1][j0],
                                   acc[2][mt][sub][c0] + sbias[2][j0],
                                   acc[3][mt][sub][c0] + sbias[3][j0], h0);
                float o1 = grustep(acc[0][mt][sub][c0 + 1] + sbias[0][j0 + 1],
                                   acc[1][mt][sub][c0 + 1] + sbias[1][j0 + 1],
                                   acc[2][mt][sub][c0 + 1] + sbias[2][j0 + 1],
                                   acc[3][mt][sub][c0 + 1] + sbias[3][j0 + 1], h1);
                orow[j0] = o0;
                orow[j0 + 1] = o1;
            }
        }
    }
    __syncthreads();

    // ---- coalesced write-out: 32 rows x 32 float4 ----
#pragma unroll
    for (int i = 0; i < 4; i++) {
        int id = tid + i * 256;
        int row = id >> 5, q = id & 31;
        int node = m0 + row;
        if (node < N_NODES)
            ((float4*)(Hw + (size_t)node * D))[q] = *(float4*)(Sg + row * 132 + q * 4);
    }
}

// ================= pooling / output (final H in buf 0) =================
__global__ void k_pool(const int* __restrict__ batch) {
    int w = (blockIdx.x * blockDim.x + threadIdx.x) >> 5;
    int lane = threadIdx.x & 31;
    if (w >= N_NODES) return;
    int g = batch[w];
    float4 acc = make_float4(0.f, 0.f, 0.f, 0.f);
    for (int t = 0; t < TT; t++) {
        float4 v = ((const float4*)(d_H + ((size_t)t * N_NODES + w) * D))[lane];
        acc.x += v.x; acc.y += v.y; acc.z += v.z; acc.w += v.w;
    }
    float* p = d_pool + (size_t)g * D + lane * 4;
    atomicAdd(p + 0, acc.x); atomicAdd(p + 1, acc.y);
    atomicAdd(p + 2, acc.z); atomicAdd(p + 3, acc.w);
    if (lane == 0) atomicAdd(&d_cnt[g], 1.f);
}

__global__ void k_out(const float* __restrict__ cw, const float* __restrict__ cb,
                      float* __restrict__ out) {
    int g = blockIdx.x, c = threadIdx.y, lane = threadIdx.x;
    float inv = 1.f / fmaxf(d_cnt[g], 1.f);
    float acc = 0.f;
    for (int j = lane; j < D; j += 32)
        acc += d_pool[(size_t)g * D + j] * inv * cw[j * 2 + c];
#pragma unroll
    for (int o = 16; o; o >>= 1) acc += __shfl_down_sync(0xffffffffu, acc, o);
    if (lane == 0) out[g * 2 + c] = acc + cb[c];
}

// ================= launch =================
extern "C" void kernel_launch(void* const* d_in, const int* in_sizes, int n_in,
                              void* d_out, int out_size) {
    const float* x      = (const float*)d_in[0];
    const int*   eidx   = (const int*)d_in[1];
    const int*   eattr  = (const int*)d_in[2];
    const int*   batch  = (const int*)d_in[3];
    const float* lin_w  = (const float*)d_in[4];
    const float* lin_b  = (const float*)d_in[5];
    const float* ggnn_w = (const float*)d_in[6];
    const float* w_ih   = (const float*)d_in[7];
    const float* w_hh   = (const float*)d_in[8];
    const float* b_ih   = (const float*)d_in[9];
    const float* b_hh   = (const float*)d_in[10];
    const float* cls_w  = (const float*)d_in[11];
    const float* cls_b  = (const float*)d_in[12];
    float* out = (float*)d_out;
    (void)in_sizes; (void)n_in; (void)out_size;

    cudaFuncSetAttribute(k_gates_mma, cudaFuncAttributeMaxDynamicSharedMemorySize, SM_DYN);

    k_prep<<<640, 256>>>();
    k_cnt2<<<(N_EDGES + 255) / 256, 256>>>(eidx, eattr);
    k_scan1<<<NBLK, 1024>>>();
    k_scan2<<<1, 1024>>>();
    k_scan3<<<NBLK, 1024>>>();
    k_fill2<<<(N_EDGES + 255) / 256, 256>>>(eidx, eattr);
    k_h0<<<(N_NODES + 63) / 64, 256>>>(x, lin_w, lin_b);
    {
        dim3 g(2, 6, TT * STEPS);
        k_q<<<g, 256>>>(ggnn_w, w_ih);
    }
    k_r<<<(TT * D * D3 + 255) / 256, 256>>>(w_hh);
    k_bsplit<<<2048, 256>>>();

    for (int s = 0; s < STEPS; s++) {
        dim3 gg(NTILE32, TT);
        k_gates_mma<<<gg, 256, SM_DYN>>>(s, b_ih, b_hh);
    }
    k_pool<<<(N_NODES * 32 + 255) / 256, 256>>>(batch);
    k_out<<<NG, dim3(32, 2)>>>(cls_w, cls_b, out);
}